// round 5
// baseline (speedup 1.0000x reference)
#include <cuda_runtime.h>
#include <math.h>

#define TQ    2000
#define KIN   400
#define MAXB  128
#define LOG2E 1.4426950408889634f
#define LN2   0.6931471805599453f
#define ANEG  (-1e7f)   // "minus infinity" (log2 domain); sinks stay huge-negative, no inf/NaN

__device__ float g_lse[MAXB * TQ];   // log2( sum_k e^{x_k} + e^{-1} ) per (b,t)
__device__ float g_losses[MAXB];

__device__ __forceinline__ float ex2(float x) {
    float r; asm("ex2.approx.ftz.f32 %0, %1;" : "=f"(r) : "f"(x)); return r;
}
__device__ __forceinline__ float lg2(float x) {
    float r; asm("lg2.approx.ftz.f32 %0, %1;" : "=f"(r) : "f"(x)); return r;
}

// ---------------------------------------------------------------------------
// Kernel 1: per-row log-softmax denominator (log2 domain), float4 vectorized.
// ---------------------------------------------------------------------------
__global__ void lse_kernel(const float* __restrict__ attn,
                           const int* __restrict__ in_lens,
                           const int* __restrict__ out_lens, int B) {
    const int warps = blockDim.x >> 5;
    const int row = blockIdx.x * warps + (threadIdx.x >> 5);
    if (row >= B * TQ) return;
    const int b = row / TQ;
    const int t = row - b * TQ;
    if (t >= out_lens[b]) return;
    const int L = in_lens[b];
    const float* p = attn + (size_t)row * KIN;
    const float4* p4 = (const float4*)p;
    const int lane = threadIdx.x & 31;
    float s = 0.f;
    const int L4 = L >> 2;
    for (int k = lane; k < L4; k += 32) {
        float4 v = __ldg(p4 + k);
        s += ex2(v.x * LOG2E) + ex2(v.y * LOG2E)
           + ex2(v.z * LOG2E) + ex2(v.w * LOG2E);
    }
    const int rem = L & 3;
    if (lane < rem) s += ex2(__ldg(p + L4 * 4 + lane) * LOG2E);
    #pragma unroll
    for (int o = 16; o; o >>= 1) s += __shfl_xor_sync(0xffffffffu, s, o);
    if (lane == 0) g_lse[row] = lg2(s + 0.36787944117144233f);  // + e^{-1}
}

// ---------------------------------------------------------------------------
// Kernel 2: CTC forward recursion. 1 CTA/batch, 832 threads, 1 state/thread.
// Warps 0-12: even (blank) states s=2i, i=tid. Warps 13-25: odd (token)
// states s=2i+1, i=tid-416. De-interleaved double-buffered alpha in SMEM
// with NEG halo at index 0. One barrier per step.
//  - distance-4 register prefetch of attn row values + lse (covers DRAM lat)
//  - MUFU-minimized logaddexp: blank 2 MUFU (abs trick), token 3 MUFU
//    (exact min/median network); diffs always <= 0, no overflow.
//  - warp-uniform band pruning: skip warps with s>2t+1 (front), s<lo (back),
//    or s>2L (dead). Skipped states provably remain at their sink values.
// ---------------------------------------------------------------------------
__global__ __launch_bounds__(832, 1)
void ctc_kernel(const float* __restrict__ attn,
                const int* __restrict__ in_lens,
                const int* __restrict__ out_lens) {
    __shared__ float bufE[2][417];
    __shared__ float bufO[2][417];

    const int b    = blockIdx.x;
    const int tid  = threadIdx.x;
    const int L    = in_lens[b];
    const int OL   = out_lens[b];
    const int last = 2 * L;

    const bool isOdd = (tid >= 416);
    const int  i     = isOdd ? tid - 416 : tid;

    for (int k = tid; k < 417; k += 832) {
        bufE[0][k] = ANEG; bufE[1][k] = ANEG;
        bufO[0][k] = ANEG; bufO[1][k] = ANEG;
    }

    const float* rowbase = attn + (size_t)b * TQ * KIN;
    const float* lsebase = g_lse + b * TQ;
    __syncthreads();

    if (tid == 0) {
        const float l0 = lsebase[0];
        bufE[0][1] = -LOG2E - l0;               // state 0: blank
        bufO[0][1] = rowbase[0] * LOG2E - l0;   // state 1: token 1
    }
    __syncthreads();

    const bool tokValid = isOdd && (i < L);

    // Warp-uniform state-index bounds for this warp
    const int i0 = i & ~31;
    const int sMin = isOdd ? (2 * i0 + 1) : (2 * i0);
    const int sMax = isOdd ? (2 * (i0 + 31) + 1) : (2 * (i0 + 31));
    const bool everActive = (sMin <= last);

    // Prime distance-4 prefetch pipeline (rows/lse t = 1..4)
    float rv0, rv1, rv2, rv3, ls0, ls1, ls2, ls3;
    {
        int tA = (1 < OL) ? 1 : OL - 1;
        int tB = (2 < OL) ? 2 : OL - 1;
        int tC = (3 < OL) ? 3 : OL - 1;
        int tD = (4 < OL) ? 4 : OL - 1;
        rv0 = tokValid ? __ldg(rowbase + (size_t)tA * KIN + i) : 0.f;
        rv1 = tokValid ? __ldg(rowbase + (size_t)tB * KIN + i) : 0.f;
        rv2 = tokValid ? __ldg(rowbase + (size_t)tC * KIN + i) : 0.f;
        rv3 = tokValid ? __ldg(rowbase + (size_t)tD * KIN + i) : 0.f;
        ls0 = __ldg(lsebase + tA);
        ls1 = __ldg(lsebase + tB);
        ls2 = __ldg(lsebase + tC);
        ls3 = __ldg(lsebase + tD);
    }

    int cb = 0;
    for (int t = 1; t < OL; t++) {
        const int hi = 2 * t + 1;
        const int lo = (last - 1) - 2 * (OL - 1 - t);
        const bool back = (sMax >= lo) && everActive;
        const bool act  = back && (sMin <= hi);
        const bool pre  = back && (sMin <= hi + 8);

        const float rvv = rv0;
        const float lsv = ls0;
        if (pre) {
            rv0 = rv1; rv1 = rv2; rv2 = rv3;
            ls0 = ls1; ls1 = ls2; ls2 = ls3;
            const int tn = (t + 4 < OL) ? (t + 4) : (OL - 1);
            rv3 = tokValid ? __ldg(rowbase + (size_t)tn * KIN + i) : 0.f;
            ls3 = __ldg(lsebase + tn);
        }

        if (act) {
            if (isOdd) {                       // token state: 3-way logaddexp
                const float em = tokValid ? fmaf(rvv, LOG2E, -lsv) : ANEG;
                const float a  = bufO[cb][i + 1];
                const float a1 = bufE[cb][i + 1];
                const float a2 = bufO[cb][i];
                const float hi2 = fmaxf(a, a1);
                const float lo2 = fminf(a, a1);
                const float m   = fmaxf(hi2, a2);
                const float med = fmaxf(lo2, fminf(hi2, a2));
                const float mn  = fminf(lo2, a2);
                const float s   = 1.f + ex2(med - m) + ex2(mn - m);
                bufO[cb ^ 1][i + 1] = m + lg2(s) + em;
            } else {                           // blank state: 2-way logaddexp
                const float em = -LOG2E - lsv;
                const float a  = bufE[cb][i + 1];
                const float a1 = bufO[cb][i];
                const float m  = fmaxf(a, a1);
                const float s  = 1.f + ex2(-fabsf(a - a1));
                bufE[cb ^ 1][i + 1] = m + lg2(s) + em;
            }
        }
        __syncthreads();
        cb ^= 1;
    }

    if (tid == 0) {
        const float aS   = bufE[cb][L + 1];    // state 2L
        const float aSm1 = bufO[cb][L];        // state 2L-1
        const float m    = fmaxf(aS, aSm1);
        const float ll2  = m + lg2(ex2(aS - m) + ex2(aSm1 - m));
        const float ll   = ll2 * LN2;
        float loss = -ll / (float)L;
        if (!(ll > -1e6f) || !isfinite(loss)) loss = 0.f;
        g_losses[b] = loss;
    }
}

// ---------------------------------------------------------------------------
// Kernel 3: mean over batch -> scalar
// ---------------------------------------------------------------------------
__global__ void reduce_kernel(float* __restrict__ out, int B) {
    float s = 0.f;
    for (int k = threadIdx.x; k < B; k += 32) s += g_losses[k];
    #pragma unroll
    for (int o = 16; o; o >>= 1) s += __shfl_xor_sync(0xffffffffu, s, o);
    if (threadIdx.x == 0) out[0] = s / (float)B;
}

extern "C" void kernel_launch(void* const* d_in, const int* in_sizes, int n_in,
                              void* d_out, int out_size) {
    const float* attn     = (const float*)d_in[0];
    const int*   in_lens  = (const int*)d_in[1];
    const int*   out_lens = (const int*)d_in[2];
    int B = in_sizes[1];
    if (B > MAXB) B = MAXB;

    const int rows = B * TQ;
    const int warps_per_block = 8;
    lse_kernel<<<(rows + warps_per_block - 1) / warps_per_block,
                 warps_per_block * 32>>>(attn, in_lens, out_lens, B);
    ctc_kernel<<<B, 832>>>(attn, in_lens, out_lens);
    reduce_kernel<<<1, 32>>>((float*)d_out, B);
}

// round 7
// speedup vs baseline: 3.4962x; 3.4962x over previous
#include <cuda_runtime.h>
#include <math.h>

#define TQ    2000
#define KIN   400
#define MAXB  128
#define LOG2E 1.4426950408889634f
#define LN2   0.6931471805599453f
#define ANEG  (-1e7f)     // log2-domain sink; stays finite, ex2(sink-real)=0

#define KSTEP 8           // recursion steps per barrier
#define PPW   24          // owned pairs per warp = 32 - KSTEP
#define NW    17          // ceil(401 / 24)
#define NT    (NW * 32)   // 544 threads

__device__ float g_lse[MAXB * TQ];   // log2( sum_k e^{x_k} + e^{-1} ) per (b,t)
__device__ float g_losses[MAXB];

__device__ __forceinline__ float ex2(float x) {
    float r; asm("ex2.approx.ftz.f32 %0, %1;" : "=f"(r) : "f"(x)); return r;
}
__device__ __forceinline__ float lg2(float x) {
    float r; asm("lg2.approx.ftz.f32 %0, %1;" : "=f"(r) : "f"(x)); return r;
}
// exact log2-domain logaddexp
__device__ __forceinline__ float lse2f(float a, float b) {
    return fmaxf(a, b) + lg2(1.f + ex2(-fabsf(a - b)));
}

// ---------------------------------------------------------------------------
// Kernel 1: per-row log-softmax denominator (log2 domain), float4 vectorized.
// ---------------------------------------------------------------------------
__global__ void lse_kernel(const float* __restrict__ attn,
                           const int* __restrict__ in_lens,
                           const int* __restrict__ out_lens, int B) {
    const int warps = blockDim.x >> 5;
    const int row = blockIdx.x * warps + (threadIdx.x >> 5);
    if (row >= B * TQ) return;
    const int b = row / TQ;
    const int t = row - b * TQ;
    if (t >= out_lens[b]) return;
    const int L = in_lens[b];
    const float* p = attn + (size_t)row * KIN;
    const float4* p4 = (const float4*)p;
    const int lane = threadIdx.x & 31;
    float s = 0.f;
    const int L4 = L >> 2;
    for (int k = lane; k < L4; k += 32) {
        float4 v = __ldg(p4 + k);
        s += ex2(v.x * LOG2E) + ex2(v.y * LOG2E)
           + ex2(v.z * LOG2E) + ex2(v.w * LOG2E);
    }
    const int rem = L & 3;
    if (lane < rem) s += ex2(__ldg(p + L4 * 4 + lane) * LOG2E);
    #pragma unroll
    for (int o = 16; o; o >>= 1) s += __shfl_xor_sync(0xffffffffu, s, o);
    if (lane == 0) g_lse[row] = lg2(s + 0.36787944117144233f);  // + e^{-1}
}

// ---------------------------------------------------------------------------
// Kernel 2: CTC forward recursion, LOG2 domain, unnormalized (lse folded out):
// track alpha' = alpha + sum_t lse2_t; subtract S once at the end.
// One CTA per batch, 544 threads, one (E=state 2i, O=state 2i+1) pair per
// thread; i = warp*24 + lane - 8, lanes 0-7 are the left halo. 8 recursion
// steps per barrier: inner steps use registers + one shfl_up (info moves at
// most 1 pair/step, so owners [lane>=8] are exact after 8 steps); exchange
// through double-buffered SMEM. Token emissions register-prefetched 1 block
// ahead (MLP=8). Blank emission is the constant -log2e.
// ---------------------------------------------------------------------------
__global__ __launch_bounds__(NT, 1)
void ctc_kernel(const float* __restrict__ attn,
                const int* __restrict__ in_lens,
                const int* __restrict__ out_lens) {
    __shared__ float Es[2][401];
    __shared__ float Os[2][401];
    __shared__ float red[NW];

    const int b    = blockIdx.x;
    const int tid  = threadIdx.x;
    const int L    = in_lens[b];
    const int OL   = out_lens[b];
    const int w    = tid >> 5;
    const int lane = tid & 31;
    const int i    = w * PPW + lane - KSTEP;   // pair index (may be <0 or >400)
    const float* rowbase = attn + (size_t)b * TQ * KIN;
    const float* lsebase = g_lse + b * TQ;

    // Block reduction: S = sum_{t<OL} lse2[t] (needed only at readout)
    {
        float s = 0.f;
        for (int t = tid; t < OL; t += NT) s += lsebase[t];
        #pragma unroll
        for (int o = 16; o; o >>= 1) s += __shfl_xor_sync(0xffffffffu, s, o);
        if (lane == 0) red[w] = s;
    }
    __syncthreads();
    float Sval = 0.f;
    if (tid == 0) {
        #pragma unroll
        for (int k = 0; k < NW; k++) Sval += red[k];
    }

    const bool tokValid = (i >= 0) && (i < L);   // token i+1 valid

    // t=0 init (unnormalized): E0' = blank logit*log2e, O0' = x(0,0)*log2e
    float E = ANEG, O = ANEG;
    if (i == 0) {
        E = -LOG2E;
        O = __ldg(rowbase) * LOG2E;
    }

    // Prefetch token emissions for t = 1..8 (already scaled by log2e)
    float rvn[KSTEP];
    #pragma unroll
    for (int j = 0; j < KSTEP; j++) {
        int t = 1 + j; if (t > OL - 1) t = OL - 1;
        rvn[j] = tokValid ? __ldg(rowbase + (size_t)t * KIN + i) * LOG2E : ANEG;
    }

    const bool owner = (lane >= KSTEP) && (i <= 400);   // i>=16 when lane>=8,w>=1
    const bool inR   = (i >= 0) && (i <= 400);

    int cb = 0;
    for (int t0 = 1; t0 < OL; t0 += KSTEP) {
        float rv[KSTEP];
        #pragma unroll
        for (int j = 0; j < KSTEP; j++) rv[j] = rvn[j];
        #pragma unroll
        for (int j = 0; j < KSTEP; j++) {
            int t = t0 + KSTEP + j; if (t > OL - 1) t = OL - 1;
            rvn[j] = tokValid ? __ldg(rowbase + (size_t)t * KIN + i) * LOG2E : ANEG;
        }

        #pragma unroll
        for (int j = 0; j < KSTEP; j++) {
            if (t0 + j >= OL) break;              // block-uniform
            const float prevO = __shfl_up_sync(0xffffffffu, O, 1);
            const float q = lse2f(E, prevO);      // LSE(alpha[2i], alpha[2i-1])
            O = lse2f(O, q) + rv[j];              // token state 2i+1
            E = q - LOG2E;                        // blank state 2i
        }

        // Exchange (owners publish; everyone reloads) — one barrier
        if (owner) { Es[cb][i] = E; Os[cb][i] = O; }
        __syncthreads();
        E = inR ? Es[cb][i] : ANEG;
        O = inR ? Os[cb][i] : ANEG;
        cb ^= 1;
    }

    // Final publish + readout
    if (owner) { Es[cb][i] = E; Os[cb][i] = O; }
    __syncthreads();
    if (tid == 0) {
        const float aS   = Es[cb][L];       // state 2L
        const float aSm1 = Os[cb][L - 1];   // state 2L-1
        const float ll   = (lse2f(aS, aSm1) - Sval) * LN2;
        float loss = -ll / (float)L;
        if (!(ll > -1e6f) || !isfinite(loss)) loss = 0.f;
        g_losses[b] = loss;
    }
}

// ---------------------------------------------------------------------------
// Kernel 3: mean over batch -> scalar
// ---------------------------------------------------------------------------
__global__ void reduce_kernel(float* __restrict__ out, int B) {
    float s = 0.f;
    for (int k = threadIdx.x; k < B; k += 32) s += g_losses[k];
    #pragma unroll
    for (int o = 16; o; o >>= 1) s += __shfl_xor_sync(0xffffffffu, s, o);
    if (threadIdx.x == 0) out[0] = s / (float)B;
}

extern "C" void kernel_launch(void* const* d_in, const int* in_sizes, int n_in,
                              void* d_out, int out_size) {
    const float* attn     = (const float*)d_in[0];
    const int*   in_lens  = (const int*)d_in[1];
    const int*   out_lens = (const int*)d_in[2];
    int B = in_sizes[1];
    if (B > MAXB) B = MAXB;

    const int rows = B * TQ;
    const int warps_per_block = 8;
    lse_kernel<<<(rows + warps_per_block - 1) / warps_per_block,
                 warps_per_block * 32>>>(attn, in_lens, out_lens, B);
    ctc_kernel<<<B, NT>>>(attn, in_lens, out_lens);
    reduce_kernel<<<1, 32>>>((float*)d_out, B);
}

// round 8
// speedup vs baseline: 5.9938x; 1.7144x over previous
#include <cuda_runtime.h>
#include <math.h>

#define TQ    2000
#define KIN   400
#define MAXB  128
#define LOG2E 1.4426950408889634f
#define LN2   0.6931471805599453f
#define ANEG  (-1e7f)     // log2-domain sink (finite; ex2(sink-real)=0)
#define PB    0.36787944117144233f  // e^{-1}: unnormalized blank prob

#define KSTEP 8           // recursion steps per barrier
#define PPW   24          // owned pairs per warp = 32 - KSTEP
#define NW    17          // ceil(401 / 24)
#define NT    (NW * 32)   // 544 threads

__device__ float g_lse[MAXB * TQ];   // log2( sum_k e^{x_k} + e^{-1} ) per (b,t)
__device__ float g_losses[MAXB];

__device__ __forceinline__ float ex2(float x) {
    float r; asm("ex2.approx.ftz.f32 %0, %1;" : "=f"(r) : "f"(x)); return r;
}
__device__ __forceinline__ float lg2(float x) {
    float r; asm("lg2.approx.ftz.f32 %0, %1;" : "=f"(r) : "f"(x)); return r;
}
__device__ __forceinline__ float lse2f(float a, float b) {
    return fmaxf(a, b) + lg2(1.f + ex2(-fabsf(a - b)));
}

// ---------------------------------------------------------------------------
// Kernel 1: per-row log-softmax denominator (log2 domain), float4 vectorized.
// ---------------------------------------------------------------------------
__global__ void lse_kernel(const float* __restrict__ attn,
                           const int* __restrict__ in_lens,
                           const int* __restrict__ out_lens, int B) {
    const int warps = blockDim.x >> 5;
    const int row = blockIdx.x * warps + (threadIdx.x >> 5);
    if (row >= B * TQ) return;
    const int b = row / TQ;
    const int t = row - b * TQ;
    if (t >= out_lens[b]) return;
    const int L = in_lens[b];
    const float* p = attn + (size_t)row * KIN;
    const float4* p4 = (const float4*)p;
    const int lane = threadIdx.x & 31;
    float s = 0.f;
    const int L4 = L >> 2;
    for (int k = lane; k < L4; k += 32) {
        float4 v = __ldg(p4 + k);
        s += ex2(v.x * LOG2E) + ex2(v.y * LOG2E)
           + ex2(v.z * LOG2E) + ex2(v.w * LOG2E);
    }
    const int rem = L & 3;
    if (lane < rem) s += ex2(__ldg(p + L4 * 4 + lane) * LOG2E);
    #pragma unroll
    for (int o = 16; o; o >>= 1) s += __shfl_xor_sync(0xffffffffu, s, o);
    if (lane == 0) g_lse[row] = lg2(s + PB);
}

// ---------------------------------------------------------------------------
// Kernel 2: CTC forward recursion, hybrid domain, softmax denominator folded
// out (subtract S = sum lse2 once at the end). One CTA/batch, 544 threads,
// one (E=state 2i, O=state 2i+1) pair per thread; i = w*24 + lane - 8,
// lanes 0-7 = left halo (info moves <=1 pair/step, owners exact after 8).
// Block boundaries in log2; inner 8 steps in LINEAR domain renormalized by
// the per-warp max (full fp32 range => flush only >=126 log2 below local
// max: provably invisible). Inner chain: shfl + 2 FMA-class ops, no MUFU
// (token probs pt=e^rv precomputed off-chain during the prefetch).
// ---------------------------------------------------------------------------
__global__ __launch_bounds__(NT, 1)
void ctc_kernel(const float* __restrict__ attn,
                const int* __restrict__ in_lens,
                const int* __restrict__ out_lens) {
    __shared__ float Es[2][401];
    __shared__ float Os[2][401];
    __shared__ float red[NW];

    const int b    = blockIdx.x;
    const int tid  = threadIdx.x;
    const int L    = in_lens[b];
    const int OL   = out_lens[b];
    const int w    = tid >> 5;
    const int lane = tid & 31;
    const int i    = w * PPW + lane - KSTEP;   // pair index (may be <0 or >400)
    const float* rowbase = attn + (size_t)b * TQ * KIN;
    const float* lsebase = g_lse + b * TQ;

    // S = sum_{t<OL} lse2[t]
    {
        float s = 0.f;
        for (int t = tid; t < OL; t += NT) s += lsebase[t];
        #pragma unroll
        for (int o = 16; o; o >>= 1) s += __shfl_xor_sync(0xffffffffu, s, o);
        if (lane == 0) red[w] = s;
    }
    __syncthreads();
    float Sval = 0.f;
    if (tid == 0) {
        #pragma unroll
        for (int k = 0; k < NW; k++) Sval += red[k];
    }

    const bool tokValid = (i >= 0) && (i < L);

    // t=0 init (unnormalized, log2): E0'=-log2e (blank), O0'=x(0,0)*log2e
    float E = ANEG, O = ANEG;
    if (i == 0) {
        E = -LOG2E;
        O = __ldg(rowbase) * LOG2E;
    }

    // Prefetch raw logits for t = 1..8
    float rvn[KSTEP];
    #pragma unroll
    for (int j = 0; j < KSTEP; j++) {
        int t = 1 + j; if (t > OL - 1) t = OL - 1;
        rvn[j] = tokValid ? __ldg(rowbase + (size_t)t * KIN + i) : ANEG;
    }

    const bool owner = (lane >= KSTEP) && (i <= 400);
    const bool inR   = (i >= 0) && (i <= 400);

    int cb = 0;
    for (int t0 = 1; t0 < OL; t0 += KSTEP) {
        // Convert this block's logits to linear probs (off critical chain)
        float pt[KSTEP];
        #pragma unroll
        for (int j = 0; j < KSTEP; j++) pt[j] = ex2(rvn[j] * LOG2E);  // e^{rv}
        // Issue next block's prefetch
        #pragma unroll
        for (int j = 0; j < KSTEP; j++) {
            int t = t0 + KSTEP + j; if (t > OL - 1) t = OL - 1;
            rvn[j] = tokValid ? __ldg(rowbase + (size_t)t * KIN + i) : ANEG;
        }

        // log2 -> linear, per-warp renorm
        float m = fmaxf(E, O);
        #pragma unroll
        for (int o = 16; o; o >>= 1) m = fmaxf(m, __shfl_xor_sync(0xffffffffu, m, o));
        float el = ex2(E - m);
        float ol = ex2(O - m);

        // 8 linear recursion steps (chain: shfl + add + fma)
        #pragma unroll
        for (int j = 0; j < KSTEP; j++) {
            if (t0 + j >= OL) break;               // CTA-uniform
            const float prevO = __shfl_up_sync(0xffffffffu, ol, 1);
            const float h = el + prevO;
            ol = (h + ol) * pt[j];
            el = h * PB;
        }

        // linear -> log2 (lg2(0)=-inf and NaN both clamp to ANEG via fmaxf)
        E = fmaxf(lg2(el) + m, ANEG);
        O = fmaxf(lg2(ol) + m, ANEG);

        // Exchange: owners publish, everyone reloads
        if (owner) { Es[cb][i] = E; Os[cb][i] = O; }
        __syncthreads();
        E = inR ? Es[cb][i] : ANEG;
        O = inR ? Os[cb][i] : ANEG;
        cb ^= 1;
    }

    // Final publish + readout
    if (owner) { Es[cb][i] = E; Os[cb][i] = O; }
    __syncthreads();
    if (tid == 0) {
        const float aS   = Es[cb][L];       // state 2L
        const float aSm1 = Os[cb][L - 1];   // state 2L-1
        const float ll   = (lse2f(aS, aSm1) - Sval) * LN2;
        float loss = -ll / (float)L;
        if (!(ll > -1e6f) || !isfinite(loss)) loss = 0.f;
        g_losses[b] = loss;
    }
}

// ---------------------------------------------------------------------------
// Kernel 3: mean over batch -> scalar
// ---------------------------------------------------------------------------
__global__ void reduce_kernel(float* __restrict__ out, int B) {
    float s = 0.f;
    for (int k = threadIdx.x; k < B; k += 32) s += g_losses[k];
    #pragma unroll
    for (int o = 16; o; o >>= 1) s += __shfl_xor_sync(0xffffffffu, s, o);
    if (threadIdx.x == 0) out[0] = s / (float)B;
}

extern "C" void kernel_launch(void* const* d_in, const int* in_sizes, int n_in,
                              void* d_out, int out_size) {
    const float* attn     = (const float*)d_in[0];
    const int*   in_lens  = (const int*)d_in[1];
    const int*   out_lens = (const int*)d_in[2];
    int B = in_sizes[1];
    if (B > MAXB) B = MAXB;

    const int rows = B * TQ;
    const int warps_per_block = 8;
    lse_kernel<<<(rows + warps_per_block - 1) / warps_per_block,
                 warps_per_block * 32>>>(attn, in_lens, out_lens, B);
    ctc_kernel<<<B, NT>>>(attn, in_lens, out_lens);
    reduce_kernel<<<1, 32>>>((float*)d_out, B);
}